// round 5
// baseline (speedup 1.0000x reference)
#include <cuda_runtime.h>
#include <cuda_bf16.h>
#include <math.h>
#include <stdint.h>

// Problem dims (fixed)
#define B_   2
#define T_   4096
#define D_   2048
#define H_   32
#define DK   64
#define BS_  128
#define NB   (T_ / BS_)     // 32
#define M_   (B_ * T_)      // 8192

// ---------------------------------------------------------------------------
// Scratch device globals
// ---------------------------------------------------------------------------
__device__ float g_Q [(size_t)M_ * D_];
__device__ float g_K [(size_t)M_ * D_];
__device__ float g_V [(size_t)M_ * D_];

__device__ __nv_bfloat16 g_xhi[(size_t)M_ * D_];
__device__ __nv_bfloat16 g_xlo[(size_t)M_ * D_];
__device__ __nv_bfloat16 g_aohi[(size_t)M_ * D_];
__device__ __nv_bfloat16 g_aolo[(size_t)M_ * D_];
__device__ __nv_bfloat16 g_whi[4][(size_t)D_ * D_];
__device__ __nv_bfloat16 g_wlo[4][(size_t)D_ * D_];

// ---------------------------------------------------------------------------
// helpers
// ---------------------------------------------------------------------------
__device__ __forceinline__ uint32_t smem_to_u32(const void* p) {
    uint32_t a;
    asm("{ .reg .u64 t; cvta.to.shared.u64 t, %1; cvt.u32.u64 %0, t; }" : "=r"(a) : "l"(p));
    return a;
}
__device__ __forceinline__ void cp16(uint32_t saddr, const void* gptr) {
    asm volatile("cp.async.cg.shared.global [%0], [%1], 16;" :: "r"(saddr), "l"(gptr));
}
#define CP_COMMIT() asm volatile("cp.async.commit_group;" ::: "memory")

#define LDSM4(r, addr) \
    asm volatile("ldmatrix.sync.aligned.m8n8.x4.shared.b16 {%0,%1,%2,%3}, [%4];" \
        : "=r"((r)[0]), "=r"((r)[1]), "=r"((r)[2]), "=r"((r)[3]) : "r"(addr))

#define MMA16816(c, a, b0v, b1v) \
    asm volatile("mma.sync.aligned.m16n8k16.row.col.f32.bf16.bf16.f32 " \
        "{%0,%1,%2,%3}, {%4,%5,%6,%7}, {%8,%9}, {%0,%1,%2,%3};" \
        : "+f"((c)[0]), "+f"((c)[1]), "+f"((c)[2]), "+f"((c)[3]) \
        : "r"((a)[0]), "r"((a)[1]), "r"((a)[2]), "r"((a)[3]), "r"(b0v), "r"(b1v))

// ---------------------------------------------------------------------------
// bf16-split tensor-core GEMM (NT): C = Ahi*Bhi + Ahi*Blo + Alo*Bhi (fp32 acc)
// 128x128 tile, BK=64, 256 threads (8 warps = 4m x 2n of 32x64), 3 stages,
// register double-buffered fragments. MMA issue reordered into 3 term-passes
// so each accumulator's reuse distance is 16 MMAs (beats HMMA latency).
// ---------------------------------------------------------------------------
#define ROWB   144
#define TILEB  (128 * ROWB)        // 18432 B
#define STAGEB (4 * TILEB)         // 73728 B
#define NSTG   3
#define GSMEM  (NSTG * STAGEB)     // 221184 B

__global__ __launch_bounds__(256, 1) void gemm_bf16x3(
    const __nv_bfloat16* __restrict__ Ahi, const __nv_bfloat16* __restrict__ Alo,
    const __nv_bfloat16* __restrict__ Bhi, const __nv_bfloat16* __restrict__ Blo,
    float* __restrict__ C, int M, int N, int K)
{
    extern __shared__ __align__(16) char smem_raw[];
    const uint32_t sbase = smem_to_u32(smem_raw);

    const int tid  = threadIdx.x;
    const int lane = tid & 31;
    const int warp = tid >> 5;
    const int wm   = warp & 3;
    const int wn   = warp >> 2;
    const int bm   = blockIdx.y * 128;
    const int bn   = blockIdx.x * 128;
    const int NT   = K / 64;

    const char* A0 = (const char*)(Ahi + (size_t)bm * K);
    const char* A1 = (const char*)(Alo + (size_t)bm * K);
    const char* B0 = (const char*)(Bhi + (size_t)bn * K);
    const char* B1 = (const char*)(Blo + (size_t)bn * K);

    const uint32_t aOff = (uint32_t)((wm * 32 + (lane & 15)) * ROWB + (lane >> 4) * 16);
    const uint32_t bOff = (uint32_t)((wn * 64 + (lane & 7) + ((lane >> 4) & 1) * 8) * ROWB
                                     + ((lane >> 3) & 1) * 16);

    float acc[2][8][4];
#pragma unroll
    for (int mt = 0; mt < 2; ++mt)
#pragma unroll
        for (int nt = 0; nt < 8; ++nt)
#pragma unroll
            for (int e = 0; e < 4; ++e) acc[mt][nt][e] = 0.0f;

    auto load_stage = [&](int kt, int s) {
        const uint32_t st = sbase + (uint32_t)s * STAGEB;
        const size_t kbyte = (size_t)kt * 128;
#pragma unroll
        for (int t = 0; t < 4; ++t) {
            const char* src = (t == 0) ? A0 : (t == 1) ? A1 : (t == 2) ? B0 : B1;
            const uint32_t tb = st + t * TILEB;
#pragma unroll
            for (int j = 0; j < 4; ++j) {
                int c  = tid + j * 256;
                int r  = c >> 3;
                int kb = (c & 7) * 16;
                cp16(tb + (uint32_t)(r * ROWB + kb),
                     src + (size_t)r * K * 2 + kbyte + kb);
            }
        }
        CP_COMMIT();
    };

    load_stage(0, 0);
    load_stage(1, 1);
    load_stage(2, 2);

#define LDFRAGS(buf, ks) do { \
    _Pragma("unroll") \
    for (int _mt = 0; _mt < 2; ++_mt) { \
        LDSM4(ah[buf][_mt], stA0 + aOff + _mt * (16 * ROWB) + (ks) * 32); \
        LDSM4(al[buf][_mt], stA1 + aOff + _mt * (16 * ROWB) + (ks) * 32); } \
    _Pragma("unroll") \
    for (int _np = 0; _np < 4; ++_np) { \
        LDSM4(bh[buf][_np], stB0 + bOff + _np * (16 * ROWB) + (ks) * 32); \
        LDSM4(bl[buf][_np], stB1 + bOff + _np * (16 * ROWB) + (ks) * 32); } \
} while (0)

    for (int kt = 0; kt < NT; ++kt) {
        const int issued = (kt + 3 < NT) ? (kt + 3) : NT;
        const int pend   = issued - kt - 1;
        if (pend >= 2)      asm volatile("cp.async.wait_group 2;" ::: "memory");
        else if (pend == 1) asm volatile("cp.async.wait_group 1;" ::: "memory");
        else                asm volatile("cp.async.wait_group 0;" ::: "memory");
        __syncthreads();

        const uint32_t st   = sbase + (uint32_t)(kt % 3) * STAGEB;
        const uint32_t stA0 = st;
        const uint32_t stA1 = st + TILEB;
        const uint32_t stB0 = st + 2 * TILEB;
        const uint32_t stB1 = st + 3 * TILEB;

        uint32_t ah[2][2][4], al[2][2][4], bh[2][4][4], bl[2][4][4];
        LDFRAGS(0, 0);

#pragma unroll
        for (int ks = 0; ks < 4; ++ks) {
            const int cur = ks & 1;
            const int nxt = cur ^ 1;
            if (ks < 3) {
                switch (ks + 1) {
                    case 1: LDFRAGS(nxt, 1); break;
                    case 2: LDFRAGS(nxt, 2); break;
                    default: LDFRAGS(nxt, 3); break;
                }
            }
            // ---- pass 1: Ahi x Bhi (16 distinct accumulators) ----
#pragma unroll
            for (int mt = 0; mt < 2; ++mt)
#pragma unroll
                for (int np = 0; np < 4; ++np) {
                    MMA16816(acc[mt][2 * np],     ah[cur][mt], bh[cur][np][0], bh[cur][np][1]);
                    MMA16816(acc[mt][2 * np + 1], ah[cur][mt], bh[cur][np][2], bh[cur][np][3]);
                }
            // ---- pass 2: Ahi x Blo ----
#pragma unroll
            for (int mt = 0; mt < 2; ++mt)
#pragma unroll
                for (int np = 0; np < 4; ++np) {
                    MMA16816(acc[mt][2 * np],     ah[cur][mt], bl[cur][np][0], bl[cur][np][1]);
                    MMA16816(acc[mt][2 * np + 1], ah[cur][mt], bl[cur][np][2], bl[cur][np][3]);
                }
            // ---- pass 3: Alo x Bhi ----
#pragma unroll
            for (int mt = 0; mt < 2; ++mt)
#pragma unroll
                for (int np = 0; np < 4; ++np) {
                    MMA16816(acc[mt][2 * np],     al[cur][mt], bh[cur][np][0], bh[cur][np][1]);
                    MMA16816(acc[mt][2 * np + 1], al[cur][mt], bh[cur][np][2], bh[cur][np][3]);
                }
        }

        __syncthreads();
        if (kt + 3 < NT) load_stage(kt + 3, kt % 3);
    }

    const int rbase = bm + wm * 32 + (lane >> 2);
    const int cbase = bn + wn * 64 + (lane & 3) * 2;
#pragma unroll
    for (int mt = 0; mt < 2; ++mt) {
#pragma unroll
        for (int nt = 0; nt < 8; ++nt) {
            int grow = rbase + mt * 16;
            int gcol = cbase + nt * 8;
            *(float2*)(C + (size_t)grow * N + gcol) =
                make_float2(acc[mt][nt][0], acc[mt][nt][1]);
            *(float2*)(C + (size_t)(grow + 8) * N + gcol) =
                make_float2(acc[mt][nt][2], acc[mt][nt][3]);
        }
    }
#undef LDFRAGS
}

// ---------------------------------------------------------------------------
// fp32 -> (bf16 hi, bf16 lo) splits
// ---------------------------------------------------------------------------
__global__ void split_kernel(const float4* __restrict__ in,
                             __nv_bfloat162* __restrict__ hi,
                             __nv_bfloat162* __restrict__ lo, int n4)
{
    int i = blockIdx.x * blockDim.x + threadIdx.x;
    if (i >= n4) return;
    float4 v = in[i];
    __nv_bfloat16 h0 = __float2bfloat16(v.x);
    __nv_bfloat16 h1 = __float2bfloat16(v.y);
    __nv_bfloat16 h2 = __float2bfloat16(v.z);
    __nv_bfloat16 h3 = __float2bfloat16(v.w);
    __nv_bfloat16 l0 = __float2bfloat16(v.x - __bfloat162float(h0));
    __nv_bfloat16 l1 = __float2bfloat16(v.y - __bfloat162float(h1));
    __nv_bfloat16 l2 = __float2bfloat16(v.z - __bfloat162float(h2));
    __nv_bfloat16 l3 = __float2bfloat16(v.w - __bfloat162float(h3));
    hi[2 * i]     = __halves2bfloat162(h0, h1);
    hi[2 * i + 1] = __halves2bfloat162(h2, h3);
    lo[2 * i]     = __halves2bfloat162(l0, l1);
    lo[2 * i + 1] = __halves2bfloat162(l2, l3);
}

struct WPtrs { const float4* w[4]; };

__global__ void split_w_kernel(WPtrs wp, __nv_bfloat162* __restrict__ hi,
                               __nv_bfloat162* __restrict__ lo, int n4)
{
    int i = blockIdx.x * blockDim.x + threadIdx.x;
    if (i >= n4) return;
    int w = blockIdx.y;
    const float4* in = wp.w[w];
    size_t off = (size_t)w * n4;
    float4 v = in[i];
    __nv_bfloat16 h0 = __float2bfloat16(v.x);
    __nv_bfloat16 h1 = __float2bfloat16(v.y);
    __nv_bfloat16 h2 = __float2bfloat16(v.z);
    __nv_bfloat16 h3 = __float2bfloat16(v.w);
    __nv_bfloat16 l0 = __float2bfloat16(v.x - __bfloat162float(h0));
    __nv_bfloat16 l1 = __float2bfloat16(v.y - __bfloat162float(h1));
    __nv_bfloat16 l2 = __float2bfloat16(v.z - __bfloat162float(h2));
    __nv_bfloat16 l3 = __float2bfloat16(v.w - __bfloat162float(h3));
    hi[2 * (off + i)]     = __halves2bfloat162(h0, h1);
    hi[2 * (off + i) + 1] = __halves2bfloat162(h2, h3);
    lo[2 * (off + i)]     = __halves2bfloat162(l0, l1);
    lo[2 * (off + i) + 1] = __halves2bfloat162(l2, l3);
}

// ---------------------------------------------------------------------------
// Sliding-window attention; writes bf16 hi/lo directly (feeds final GEMM).
// ---------------------------------------------------------------------------
__global__ __launch_bounds__(128) void swa_kernel(
    const float* __restrict__ Q, const float* __restrict__ Kt,
    const float* __restrict__ Vt,
    __nv_bfloat16* __restrict__ Ohi, __nv_bfloat16* __restrict__ Olo)
{
    const int i = blockIdx.x;
    const int h = blockIdx.y;
    const int b = blockIdx.z;
    const int r = threadIdx.x;

    __shared__ __align__(16) float Kc[64][64];
    __shared__ __align__(16) float Vc[64][64];

    const float scale = 0.125f;

    float q[DK];
    const size_t rowoff = ((size_t)b * T_ + (size_t)i * BS_ + r) * D_ + (size_t)h * DK;
#pragma unroll
    for (int d = 0; d < DK; d += 4) {
        float4 t = *(const float4*)(Q + rowoff + d);
        q[d] = t.x; q[d + 1] = t.y; q[d + 2] = t.z; q[d + 3] = t.w;
    }

    float o[DK];
#pragma unroll
    for (int d = 0; d < DK; ++d) o[d] = 0.0f;
    float mval = -INFINITY;
    float l = 0.0f;

    const int base_t  = (i - 1) * BS_;
    const int cmin    = (i == 0) ? 128 : r;
    const int cmax    = r + 128;
    const int c_start = (i == 0) ? 128 : 0;

    const int sub = r >> 4;
    const int d4  = (r & 15) * 4;

    for (int c0 = c_start; c0 < 256; c0 += 64) {
        __syncthreads();
#pragma unroll
        for (int it = 0; it < 8; ++it) {
            int j  = it * 8 + sub;
            int tk = base_t + c0 + j;
            size_t off = ((size_t)b * T_ + tk) * D_ + (size_t)h * DK + d4;
            float4 kv = *(const float4*)(Kt + off);
            float4 vv = *(const float4*)(Vt + off);
            *(float4*)&Kc[j][d4] = kv;
            *(float4*)&Vc[j][d4] = vv;
        }
        __syncthreads();

        for (int j = 0; j < 64; ++j) {
            const int c = c0 + j;
            if (c < cmin || c > cmax) continue;

            float s0 = 0.0f, s1 = 0.0f;
#pragma unroll
            for (int d = 0; d < 32; d += 4) {
                float4 k4 = *(const float4*)&Kc[j][d];
                s0 += q[d] * k4.x + q[d + 1] * k4.y + q[d + 2] * k4.z + q[d + 3] * k4.w;
            }
#pragma unroll
            for (int d = 32; d < 64; d += 4) {
                float4 k4 = *(const float4*)&Kc[j][d];
                s1 += q[d] * k4.x + q[d + 1] * k4.y + q[d + 2] * k4.z + q[d + 3] * k4.w;
            }
            float s = (s0 + s1) * scale;

            if (s > mval) {
                float corr = __expf(mval - s);
                l *= corr;
#pragma unroll
                for (int d = 0; d < DK; ++d) o[d] *= corr;
                mval = s;
            }
            float p = __expf(s - mval);
            l += p;
#pragma unroll
            for (int d = 0; d < DK; d += 4) {
                float4 v4 = *(const float4*)&Vc[j][d];
                o[d]     += p * v4.x;
                o[d + 1] += p * v4.y;
                o[d + 2] += p * v4.z;
                o[d + 3] += p * v4.w;
            }
        }
    }

    const float inv = 1.0f / l;
    __nv_bfloat162* hp = (__nv_bfloat162*)(Ohi + rowoff);
    __nv_bfloat162* lp = (__nv_bfloat162*)(Olo + rowoff);
#pragma unroll
    for (int d = 0; d < DK; d += 2) {
        float a0 = o[d] * inv, a1 = o[d + 1] * inv;
        __nv_bfloat16 h0 = __float2bfloat16(a0);
        __nv_bfloat16 h1 = __float2bfloat16(a1);
        __nv_bfloat16 l0 = __float2bfloat16(a0 - __bfloat162float(h0));
        __nv_bfloat16 l1 = __float2bfloat16(a1 - __bfloat162float(h1));
        hp[d >> 1] = __halves2bfloat162(h0, h1);
        lp[d >> 1] = __halves2bfloat162(l0, l1);
    }
}

// ---------------------------------------------------------------------------
// Launch
// ---------------------------------------------------------------------------
extern "C" void kernel_launch(void* const* d_in, const int* in_sizes, int n_in,
                              void* d_out, int out_size)
{
    const float* x  = (const float*)d_in[0];
    float* out = (float*)d_out;

    float *qp, *kp, *vp;
    cudaGetSymbolAddress((void**)&qp,  g_Q);
    cudaGetSymbolAddress((void**)&kp,  g_K);
    cudaGetSymbolAddress((void**)&vp,  g_V);
    __nv_bfloat16 *xhi, *xlo, *aohi, *aolo, *whi, *wlo;
    cudaGetSymbolAddress((void**)&xhi,  g_xhi);
    cudaGetSymbolAddress((void**)&xlo,  g_xlo);
    cudaGetSymbolAddress((void**)&aohi, g_aohi);
    cudaGetSymbolAddress((void**)&aolo, g_aolo);
    cudaGetSymbolAddress((void**)&whi,  g_whi);
    cudaGetSymbolAddress((void**)&wlo,  g_wlo);

    cudaFuncSetAttribute(gemm_bf16x3, cudaFuncAttributeMaxDynamicSharedMemorySize, GSMEM);

    const int nX  = M_ * D_;
    const int nW  = D_ * D_;
    const int thr = 256;

    split_kernel<<<(nX / 4 + thr - 1) / thr, thr>>>(
        (const float4*)x, (__nv_bfloat162*)xhi, (__nv_bfloat162*)xlo, nX / 4);

    WPtrs wp;
    wp.w[0] = (const float4*)d_in[1];
    wp.w[1] = (const float4*)d_in[2];
    wp.w[2] = (const float4*)d_in[3];
    wp.w[3] = (const float4*)d_in[4];
    dim3 gw((nW / 4 + thr - 1) / thr, 4);
    split_w_kernel<<<gw, thr>>>(wp, (__nv_bfloat162*)whi, (__nv_bfloat162*)wlo, nW / 4);

    dim3 gg(D_ / 128, M_ / 128);        // (16, 64)
    gemm_bf16x3<<<gg, 256, GSMEM>>>(xhi, xlo, whi + 0 * (size_t)nW, wlo + 0 * (size_t)nW, qp, M_, D_, D_);
    gemm_bf16x3<<<gg, 256, GSMEM>>>(xhi, xlo, whi + 1 * (size_t)nW, wlo + 1 * (size_t)nW, kp, M_, D_, D_);
    gemm_bf16x3<<<gg, 256, GSMEM>>>(xhi, xlo, whi + 2 * (size_t)nW, wlo + 2 * (size_t)nW, vp, M_, D_, D_);

    dim3 ga(NB, H_, B_);
    swa_kernel<<<ga, 128>>>(qp, kp, vp, aohi, aolo);

    gemm_bf16x3<<<gg, 256, GSMEM>>>(aohi, aolo, whi + 3 * (size_t)nW, wlo + 3 * (size_t)nW, out, M_, D_, D_);
}

// round 6
// speedup vs baseline: 1.0426x; 1.0426x over previous
#include <cuda_runtime.h>
#include <cuda_bf16.h>
#include <math.h>
#include <stdint.h>

// Problem dims (fixed)
#define B_   2
#define T_   4096
#define D_   2048
#define H_   32
#define DK   64
#define BS_  128
#define NB   (T_ / BS_)     // 32
#define M_   (B_ * T_)      // 8192

// ---------------------------------------------------------------------------
// Scratch device globals
// ---------------------------------------------------------------------------
__device__ float g_Q [(size_t)M_ * D_];
__device__ float g_K [(size_t)M_ * D_];
__device__ float g_V [(size_t)M_ * D_];

__device__ __nv_bfloat16 g_xhi[(size_t)M_ * D_];
__device__ __nv_bfloat16 g_xlo[(size_t)M_ * D_];
__device__ __nv_bfloat16 g_aohi[(size_t)M_ * D_];
__device__ __nv_bfloat16 g_aolo[(size_t)M_ * D_];
__device__ __nv_bfloat16 g_whi[4][(size_t)D_ * D_];
__device__ __nv_bfloat16 g_wlo[4][(size_t)D_ * D_];

// ---------------------------------------------------------------------------
// helpers
// ---------------------------------------------------------------------------
__device__ __forceinline__ uint32_t smem_to_u32(const void* p) {
    uint32_t a;
    asm("{ .reg .u64 t; cvta.to.shared.u64 t, %1; cvt.u32.u64 %0, t; }" : "=r"(a) : "l"(p));
    return a;
}
__device__ __forceinline__ void cp16(uint32_t saddr, const void* gptr) {
    asm volatile("cp.async.cg.shared.global [%0], [%1], 16;" :: "r"(saddr), "l"(gptr));
}
#define CP_COMMIT() asm volatile("cp.async.commit_group;" ::: "memory")

#define LDSM4(r, addr) \
    asm volatile("ldmatrix.sync.aligned.m8n8.x4.shared.b16 {%0,%1,%2,%3}, [%4];" \
        : "=r"((r)[0]), "=r"((r)[1]), "=r"((r)[2]), "=r"((r)[3]) : "r"(addr))

#define MMA16816(c, a, b0v, b1v) \
    asm volatile("mma.sync.aligned.m16n8k16.row.col.f32.bf16.bf16.f32 " \
        "{%0,%1,%2,%3}, {%4,%5,%6,%7}, {%8,%9}, {%0,%1,%2,%3};" \
        : "+f"((c)[0]), "+f"((c)[1]), "+f"((c)[2]), "+f"((c)[3]) \
        : "r"((a)[0]), "r"((a)[1]), "r"((a)[2]), "r"((a)[3]), "r"(b0v), "r"(b1v))

// ---------------------------------------------------------------------------
// bf16-split tensor-core GEMM (NT): C = Ahi*Bhi + Ahi*Blo + Alo*Bhi (fp32 acc)
// CTA tile 128x64, BK=64, 256 threads (8 warps = 4m x 2n of 32x32),
// 2 cp.async stages, single-buffered fragments, 2 CTAs/SM.
// ---------------------------------------------------------------------------
#define ROWB    144
#define ATILEB  (128 * ROWB)           // 18432
#define BTILEB  (64  * ROWB)           // 9216
#define STAGEB  (2 * ATILEB + 2 * BTILEB)   // 55296
#define GSMEM   (2 * STAGEB)           // 110592

__global__ __launch_bounds__(256, 2) void gemm_bf16x3(
    const __nv_bfloat16* __restrict__ Ahi, const __nv_bfloat16* __restrict__ Alo,
    const __nv_bfloat16* __restrict__ Bhi, const __nv_bfloat16* __restrict__ Blo,
    float* __restrict__ C, int M, int N, int K)
{
    extern __shared__ __align__(16) char smem_raw[];
    const uint32_t sbase = smem_to_u32(smem_raw);

    const int tid  = threadIdx.x;
    const int lane = tid & 31;
    const int warp = tid >> 5;
    const int wm   = warp & 3;          // 4 m-warps of 32 rows
    const int wn   = warp >> 2;         // 2 n-warps of 32 cols
    const int bm   = blockIdx.y * 128;
    const int bn   = blockIdx.x * 64;
    const int NT   = K / 64;

    const char* A0 = (const char*)(Ahi + (size_t)bm * K);
    const char* A1 = (const char*)(Alo + (size_t)bm * K);
    const char* B0 = (const char*)(Bhi + (size_t)bn * K);
    const char* B1 = (const char*)(Blo + (size_t)bn * K);

    const uint32_t aOff = (uint32_t)((wm * 32 + (lane & 15)) * ROWB + (lane >> 4) * 16);
    const uint32_t bOff = (uint32_t)((wn * 32 + (lane & 7) + ((lane >> 4) & 1) * 8) * ROWB
                                     + ((lane >> 3) & 1) * 16);

    float acc[2][4][4];
#pragma unroll
    for (int mt = 0; mt < 2; ++mt)
#pragma unroll
        for (int nt = 0; nt < 4; ++nt)
#pragma unroll
            for (int e = 0; e < 4; ++e) acc[mt][nt][e] = 0.0f;

    // stage loader: A tiles 128 rows x 8 chunks (4/thread), B tiles 64 x 8 (2/thread)
    auto load_stage = [&](int kt, int s) {
        const uint32_t st = sbase + (uint32_t)s * STAGEB;
        const size_t kbyte = (size_t)kt * 128;
#pragma unroll
        for (int t = 0; t < 2; ++t) {
            const char* src = t ? A1 : A0;
            const uint32_t tb = st + t * ATILEB;
#pragma unroll
            for (int j = 0; j < 4; ++j) {
                int c  = tid + j * 256;          // 0..1023
                int r  = c >> 3;                 // 0..127
                int kb = (c & 7) * 16;
                cp16(tb + (uint32_t)(r * ROWB + kb),
                     src + (size_t)r * K * 2 + kbyte + kb);
            }
        }
#pragma unroll
        for (int t = 0; t < 2; ++t) {
            const char* src = t ? B1 : B0;
            const uint32_t tb = st + 2 * ATILEB + t * BTILEB;
#pragma unroll
            for (int j = 0; j < 2; ++j) {
                int c  = tid + j * 256;          // 0..511
                int r  = c >> 3;                 // 0..63
                int kb = (c & 7) * 16;
                cp16(tb + (uint32_t)(r * ROWB + kb),
                     src + (size_t)r * K * 2 + kbyte + kb);
            }
        }
        CP_COMMIT();
    };

    load_stage(0, 0);

#define LDFRAGS(ks) do { \
    _Pragma("unroll") \
    for (int _mt = 0; _mt < 2; ++_mt) { \
        LDSM4(ah[_mt], stA0 + aOff + _mt * (16 * ROWB) + (ks) * 32); \
        LDSM4(al[_mt], stA1 + aOff + _mt * (16 * ROWB) + (ks) * 32); } \
    _Pragma("unroll") \
    for (int _np = 0; _np < 2; ++_np) { \
        LDSM4(bh[_np], stB0 + bOff + _np * (16 * ROWB) + (ks) * 32); \
        LDSM4(bl[_np], stB1 + bOff + _np * (16 * ROWB) + (ks) * 32); } \
} while (0)

    for (int kt = 0; kt < NT; ++kt) {
        if (kt + 1 < NT) {
            load_stage(kt + 1, (kt + 1) & 1);
            asm volatile("cp.async.wait_group 1;" ::: "memory");
        } else {
            asm volatile("cp.async.wait_group 0;" ::: "memory");
        }
        __syncthreads();

        const uint32_t st   = sbase + (uint32_t)(kt & 1) * STAGEB;
        const uint32_t stA0 = st;
        const uint32_t stA1 = st + ATILEB;
        const uint32_t stB0 = st + 2 * ATILEB;
        const uint32_t stB1 = st + 2 * ATILEB + BTILEB;

#pragma unroll
        for (int ks = 0; ks < 4; ++ks) {
            uint32_t ah[2][4], al[2][4], bh[2][4], bl[2][4];
            switch (ks) {                         // keep immediate smem offsets
                case 0: LDFRAGS(0); break;
                case 1: LDFRAGS(1); break;
                case 2: LDFRAGS(2); break;
                default: LDFRAGS(3); break;
            }
            // pass 1: Ahi x Bhi
#pragma unroll
            for (int mt = 0; mt < 2; ++mt)
#pragma unroll
                for (int np = 0; np < 2; ++np) {
                    MMA16816(acc[mt][2 * np],     ah[mt], bh[np][0], bh[np][1]);
                    MMA16816(acc[mt][2 * np + 1], ah[mt], bh[np][2], bh[np][3]);
                }
            // pass 2: Ahi x Blo
#pragma unroll
            for (int mt = 0; mt < 2; ++mt)
#pragma unroll
                for (int np = 0; np < 2; ++np) {
                    MMA16816(acc[mt][2 * np],     ah[mt], bl[np][0], bl[np][1]);
                    MMA16816(acc[mt][2 * np + 1], ah[mt], bl[np][2], bl[np][3]);
                }
            // pass 3: Alo x Bhi
#pragma unroll
            for (int mt = 0; mt < 2; ++mt)
#pragma unroll
                for (int np = 0; np < 2; ++np) {
                    MMA16816(acc[mt][2 * np],     al[mt], bh[np][0], bh[np][1]);
                    MMA16816(acc[mt][2 * np + 1], al[mt], bh[np][2], bh[np][3]);
                }
        }

        __syncthreads();
    }

    const int rbase = bm + wm * 32 + (lane >> 2);
    const int cbase = bn + wn * 32 + (lane & 3) * 2;
#pragma unroll
    for (int mt = 0; mt < 2; ++mt) {
#pragma unroll
        for (int nt = 0; nt < 4; ++nt) {
            int grow = rbase + mt * 16;
            int gcol = cbase + nt * 8;
            *(float2*)(C + (size_t)grow * N + gcol) =
                make_float2(acc[mt][nt][0], acc[mt][nt][1]);
            *(float2*)(C + (size_t)(grow + 8) * N + gcol) =
                make_float2(acc[mt][nt][2], acc[mt][nt][3]);
        }
    }
#undef LDFRAGS
}

// ---------------------------------------------------------------------------
// fp32 -> (bf16 hi, bf16 lo) splits
// ---------------------------------------------------------------------------
__global__ void split_kernel(const float4* __restrict__ in,
                             __nv_bfloat162* __restrict__ hi,
                             __nv_bfloat162* __restrict__ lo, int n4)
{
    int i = blockIdx.x * blockDim.x + threadIdx.x;
    if (i >= n4) return;
    float4 v = in[i];
    __nv_bfloat16 h0 = __float2bfloat16(v.x);
    __nv_bfloat16 h1 = __float2bfloat16(v.y);
    __nv_bfloat16 h2 = __float2bfloat16(v.z);
    __nv_bfloat16 h3 = __float2bfloat16(v.w);
    __nv_bfloat16 l0 = __float2bfloat16(v.x - __bfloat162float(h0));
    __nv_bfloat16 l1 = __float2bfloat16(v.y - __bfloat162float(h1));
    __nv_bfloat16 l2 = __float2bfloat16(v.z - __bfloat162float(h2));
    __nv_bfloat16 l3 = __float2bfloat16(v.w - __bfloat162float(h3));
    hi[2 * i]     = __halves2bfloat162(h0, h1);
    hi[2 * i + 1] = __halves2bfloat162(h2, h3);
    lo[2 * i]     = __halves2bfloat162(l0, l1);
    lo[2 * i + 1] = __halves2bfloat162(l2, l3);
}

struct WPtrs { const float4* w[4]; };

__global__ void split_w_kernel(WPtrs wp, __nv_bfloat162* __restrict__ hi,
                               __nv_bfloat162* __restrict__ lo, int n4)
{
    int i = blockIdx.x * blockDim.x + threadIdx.x;
    if (i >= n4) return;
    int w = blockIdx.y;
    const float4* in = wp.w[w];
    size_t off = (size_t)w * n4;
    float4 v = in[i];
    __nv_bfloat16 h0 = __float2bfloat16(v.x);
    __nv_bfloat16 h1 = __float2bfloat16(v.y);
    __nv_bfloat16 h2 = __float2bfloat16(v.z);
    __nv_bfloat16 h3 = __float2bfloat16(v.w);
    __nv_bfloat16 l0 = __float2bfloat16(v.x - __bfloat162float(h0));
    __nv_bfloat16 l1 = __float2bfloat16(v.y - __bfloat162float(h1));
    __nv_bfloat16 l2 = __float2bfloat16(v.z - __bfloat162float(h2));
    __nv_bfloat16 l3 = __float2bfloat16(v.w - __bfloat162float(h3));
    hi[2 * (off + i)]     = __halves2bfloat162(h0, h1);
    hi[2 * (off + i) + 1] = __halves2bfloat162(h2, h3);
    lo[2 * (off + i)]     = __halves2bfloat162(l0, l1);
    lo[2 * (off + i) + 1] = __halves2bfloat162(l2, l3);
}

// ---------------------------------------------------------------------------
// Sliding-window attention; writes bf16 hi/lo directly (feeds final GEMM).
// ---------------------------------------------------------------------------
__global__ __launch_bounds__(128) void swa_kernel(
    const float* __restrict__ Q, const float* __restrict__ Kt,
    const float* __restrict__ Vt,
    __nv_bfloat16* __restrict__ Ohi, __nv_bfloat16* __restrict__ Olo)
{
    const int i = blockIdx.x;
    const int h = blockIdx.y;
    const int b = blockIdx.z;
    const int r = threadIdx.x;

    __shared__ __align__(16) float Kc[64][64];
    __shared__ __align__(16) float Vc[64][64];

    const float scale = 0.125f;

    float q[DK];
    const size_t rowoff = ((size_t)b * T_ + (size_t)i * BS_ + r) * D_ + (size_t)h * DK;
#pragma unroll
    for (int d = 0; d < DK; d += 4) {
        float4 t = *(const float4*)(Q + rowoff + d);
        q[d] = t.x; q[d + 1] = t.y; q[d + 2] = t.z; q[d + 3] = t.w;
    }

    float o[DK];
#pragma unroll
    for (int d = 0; d < DK; ++d) o[d] = 0.0f;
    float mval = -INFINITY;
    float l = 0.0f;

    const int base_t  = (i - 1) * BS_;
    const int cmin    = (i == 0) ? 128 : r;
    const int cmax    = r + 128;
    const int c_start = (i == 0) ? 128 : 0;

    const int sub = r >> 4;
    const int d4  = (r & 15) * 4;

    for (int c0 = c_start; c0 < 256; c0 += 64) {
        __syncthreads();
#pragma unroll
        for (int it = 0; it < 8; ++it) {
            int j  = it * 8 + sub;
            int tk = base_t + c0 + j;
            size_t off = ((size_t)b * T_ + tk) * D_ + (size_t)h * DK + d4;
            float4 kv = *(const float4*)(Kt + off);
            float4 vv = *(const float4*)(Vt + off);
            *(float4*)&Kc[j][d4] = kv;
            *(float4*)&Vc[j][d4] = vv;
        }
        __syncthreads();

        for (int j = 0; j < 64; ++j) {
            const int c = c0 + j;
            if (c < cmin || c > cmax) continue;

            float s0 = 0.0f, s1 = 0.0f;
#pragma unroll
            for (int d = 0; d < 32; d += 4) {
                float4 k4 = *(const float4*)&Kc[j][d];
                s0 += q[d] * k4.x + q[d + 1] * k4.y + q[d + 2] * k4.z + q[d + 3] * k4.w;
            }
#pragma unroll
            for (int d = 32; d < 64; d += 4) {
                float4 k4 = *(const float4*)&Kc[j][d];
                s1 += q[d] * k4.x + q[d + 1] * k4.y + q[d + 2] * k4.z + q[d + 3] * k4.w;
            }
            float s = (s0 + s1) * scale;

            if (s > mval) {
                float corr = __expf(mval - s);
                l *= corr;
#pragma unroll
                for (int d = 0; d < DK; ++d) o[d] *= corr;
                mval = s;
            }
            float p = __expf(s - mval);
            l += p;
#pragma unroll
            for (int d = 0; d < DK; d += 4) {
                float4 v4 = *(const float4*)&Vc[j][d];
                o[d]     += p * v4.x;
                o[d + 1] += p * v4.y;
                o[d + 2] += p * v4.z;
                o[d + 3] += p * v4.w;
            }
        }
    }

    const float inv = 1.0f / l;
    __nv_bfloat162* hp = (__nv_bfloat162*)(Ohi + rowoff);
    __nv_bfloat162* lp = (__nv_bfloat162*)(Olo + rowoff);
#pragma unroll
    for (int d = 0; d < DK; d += 2) {
        float a0 = o[d] * inv, a1 = o[d + 1] * inv;
        __nv_bfloat16 h0 = __float2bfloat16(a0);
        __nv_bfloat16 h1 = __float2bfloat16(a1);
        __nv_bfloat16 l0 = __float2bfloat16(a0 - __bfloat162float(h0));
        __nv_bfloat16 l1 = __float2bfloat16(a1 - __bfloat162float(h1));
        hp[d >> 1] = __halves2bfloat162(h0, h1);
        lp[d >> 1] = __halves2bfloat162(l0, l1);
    }
}

// ---------------------------------------------------------------------------
// Launch
// ---------------------------------------------------------------------------
extern "C" void kernel_launch(void* const* d_in, const int* in_sizes, int n_in,
                              void* d_out, int out_size)
{
    const float* x  = (const float*)d_in[0];
    float* out = (float*)d_out;

    float *qp, *kp, *vp;
    cudaGetSymbolAddress((void**)&qp,  g_Q);
    cudaGetSymbolAddress((void**)&kp,  g_K);
    cudaGetSymbolAddress((void**)&vp,  g_V);
    __nv_bfloat16 *xhi, *xlo, *aohi, *aolo, *whi, *wlo;
    cudaGetSymbolAddress((void**)&xhi,  g_xhi);
    cudaGetSymbolAddress((void**)&xlo,  g_xlo);
    cudaGetSymbolAddress((void**)&aohi, g_aohi);
    cudaGetSymbolAddress((void**)&aolo, g_aolo);
    cudaGetSymbolAddress((void**)&whi,  g_whi);
    cudaGetSymbolAddress((void**)&wlo,  g_wlo);

    cudaFuncSetAttribute(gemm_bf16x3, cudaFuncAttributeMaxDynamicSharedMemorySize, GSMEM);

    const int nX  = M_ * D_;
    const int nW  = D_ * D_;
    const int thr = 256;

    split_kernel<<<(nX / 4 + thr - 1) / thr, thr>>>(
        (const float4*)x, (__nv_bfloat162*)xhi, (__nv_bfloat162*)xlo, nX / 4);

    WPtrs wp;
    wp.w[0] = (const float4*)d_in[1];
    wp.w[1] = (const float4*)d_in[2];
    wp.w[2] = (const float4*)d_in[3];
    wp.w[3] = (const float4*)d_in[4];
    dim3 gw((nW / 4 + thr - 1) / thr, 4);
    split_w_kernel<<<gw, thr>>>(wp, (__nv_bfloat162*)whi, (__nv_bfloat162*)wlo, nW / 4);

    dim3 gg(D_ / 64, M_ / 128);         // (32, 64)
    gemm_bf16x3<<<gg, 256, GSMEM>>>(xhi, xlo, whi + 0 * (size_t)nW, wlo + 0 * (size_t)nW, qp, M_, D_, D_);
    gemm_bf16x3<<<gg, 256, GSMEM>>>(xhi, xlo, whi + 1 * (size_t)nW, wlo + 1 * (size_t)nW, kp, M_, D_, D_);
    gemm_bf16x3<<<gg, 256, GSMEM>>>(xhi, xlo, whi + 2 * (size_t)nW, wlo + 2 * (size_t)nW, vp, M_, D_, D_);

    dim3 ga(NB, H_, B_);
    swa_kernel<<<ga, 128>>>(qp, kp, vp, aohi, aolo);

    gemm_bf16x3<<<gg, 256, GSMEM>>>(aohi, aolo, whi + 3 * (size_t)nW, wlo + 3 * (size_t)nW, out, M_, D_, D_);
}

// round 7
// speedup vs baseline: 1.0457x; 1.0029x over previous
#include <cuda_runtime.h>
#include <cuda_bf16.h>
#include <math.h>
#include <stdint.h>

// Problem dims (fixed)
#define B_   2
#define T_   4096
#define D_   2048
#define H_   32
#define DK   64
#define BS_  128
#define NB   (T_ / BS_)     // 32
#define M_   (B_ * T_)      // 8192

// ---------------------------------------------------------------------------
// Scratch device globals
// ---------------------------------------------------------------------------
__device__ float g_Q [(size_t)M_ * D_];
__device__ float g_K [(size_t)M_ * D_];
__device__ float g_V [(size_t)M_ * D_];

__device__ __nv_bfloat16 g_xhi[(size_t)M_ * D_];
__device__ __nv_bfloat16 g_xlo[(size_t)M_ * D_];
__device__ __nv_bfloat16 g_aohi[(size_t)M_ * D_];
__device__ __nv_bfloat16 g_aolo[(size_t)M_ * D_];
__device__ __nv_bfloat16 g_whi[4][(size_t)D_ * D_];
__device__ __nv_bfloat16 g_wlo[4][(size_t)D_ * D_];

// ---------------------------------------------------------------------------
// helpers
// ---------------------------------------------------------------------------
__device__ __forceinline__ uint32_t smem_to_u32(const void* p) {
    uint32_t a;
    asm("{ .reg .u64 t; cvta.to.shared.u64 t, %1; cvt.u32.u64 %0, t; }" : "=r"(a) : "l"(p));
    return a;
}
__device__ __forceinline__ void cp16(uint32_t saddr, const void* gptr) {
    asm volatile("cp.async.cg.shared.global [%0], [%1], 16;" :: "r"(saddr), "l"(gptr));
}
#define CP_COMMIT() asm volatile("cp.async.commit_group;" ::: "memory")

#define LDSM4(r, addr) \
    asm volatile("ldmatrix.sync.aligned.m8n8.x4.shared.b16 {%0,%1,%2,%3}, [%4];" \
        : "=r"((r)[0]), "=r"((r)[1]), "=r"((r)[2]), "=r"((r)[3]) : "r"(addr))

#define MMA16816(c, a, b0v, b1v) \
    asm volatile("mma.sync.aligned.m16n8k16.row.col.f32.bf16.bf16.f32 " \
        "{%0,%1,%2,%3}, {%4,%5,%6,%7}, {%8,%9}, {%0,%1,%2,%3};" \
        : "+f"((c)[0]), "+f"((c)[1]), "+f"((c)[2]), "+f"((c)[3]) \
        : "r"((a)[0]), "r"((a)[1]), "r"((a)[2]), "r"((a)[3]), "r"(b0v), "r"(b1v))

// ---------------------------------------------------------------------------
// bf16-split tensor-core GEMM (NT): C = Ahi*Bhi + Ahi*Blo + Alo*Bhi (fp32 acc)
// CTA tile 128x64, BK=64, 128 threads (4 warps = 2m x 2n, warp tile 64x32),
// 2 cp.async stages, fragment double-buffering across ks, 2 CTAs/SM.
// ---------------------------------------------------------------------------
#define ROWB    144
#define ATILEB  (128 * ROWB)           // 18432
#define BTILEB  (64  * ROWB)           // 9216
#define STAGEB  (2 * ATILEB + 2 * BTILEB)   // 55296
#define GSMEM   (2 * STAGEB)           // 110592

__global__ __launch_bounds__(128, 2) void gemm_bf16x3(
    const __nv_bfloat16* __restrict__ Ahi, const __nv_bfloat16* __restrict__ Alo,
    const __nv_bfloat16* __restrict__ Bhi, const __nv_bfloat16* __restrict__ Blo,
    float* __restrict__ C, int M, int N, int K)
{
    extern __shared__ __align__(16) char smem_raw[];
    const uint32_t sbase = smem_to_u32(smem_raw);

    const int tid  = threadIdx.x;
    const int lane = tid & 31;
    const int warp = tid >> 5;
    const int wm   = warp & 1;          // 2 m-warps of 64 rows
    const int wn   = warp >> 1;         // 2 n-warps of 32 cols
    const int bm   = blockIdx.y * 128;
    const int bn   = blockIdx.x * 64;
    const int NT   = K / 64;

    const char* A0 = (const char*)(Ahi + (size_t)bm * K);
    const char* A1 = (const char*)(Alo + (size_t)bm * K);
    const char* B0 = (const char*)(Bhi + (size_t)bn * K);
    const char* B1 = (const char*)(Blo + (size_t)bn * K);

    const uint32_t aOff = (uint32_t)((wm * 64 + (lane & 15)) * ROWB + (lane >> 4) * 16);
    const uint32_t bOff = (uint32_t)((wn * 32 + (lane & 7) + ((lane >> 4) & 1) * 8) * ROWB
                                     + ((lane >> 3) & 1) * 16);

    float acc[4][4][4];                 // [m-tile][n-tile(8col)][frag]
#pragma unroll
    for (int mt = 0; mt < 4; ++mt)
#pragma unroll
        for (int nt = 0; nt < 4; ++nt)
#pragma unroll
            for (int e = 0; e < 4; ++e) acc[mt][nt][e] = 0.0f;

    // stage loader (128 thr): A tiles 1024 chunks (8/thr), B tiles 512 (4/thr)
    auto load_stage = [&](int kt, int s) {
        const uint32_t st = sbase + (uint32_t)s * STAGEB;
        const size_t kbyte = (size_t)kt * 128;
#pragma unroll
        for (int t = 0; t < 2; ++t) {
            const char* src = t ? A1 : A0;
            const uint32_t tb = st + t * ATILEB;
#pragma unroll
            for (int j = 0; j < 8; ++j) {
                int c  = tid + j * 128;          // 0..1023
                int r  = c >> 3;                 // 0..127
                int kb = (c & 7) * 16;
                cp16(tb + (uint32_t)(r * ROWB + kb),
                     src + (size_t)r * K * 2 + kbyte + kb);
            }
        }
#pragma unroll
        for (int t = 0; t < 2; ++t) {
            const char* src = t ? B1 : B0;
            const uint32_t tb = st + 2 * ATILEB + t * BTILEB;
#pragma unroll
            for (int j = 0; j < 4; ++j) {
                int c  = tid + j * 128;          // 0..511
                int r  = c >> 3;                 // 0..63
                int kb = (c & 7) * 16;
                cp16(tb + (uint32_t)(r * ROWB + kb),
                     src + (size_t)r * K * 2 + kbyte + kb);
            }
        }
        CP_COMMIT();
    };

    load_stage(0, 0);

#define LDFRAGS(buf, ks) do { \
    _Pragma("unroll") \
    for (int _mt = 0; _mt < 4; ++_mt) { \
        LDSM4(ah[buf][_mt], stA0 + aOff + _mt * (16 * ROWB) + (ks) * 32); \
        LDSM4(al[buf][_mt], stA1 + aOff + _mt * (16 * ROWB) + (ks) * 32); } \
    _Pragma("unroll") \
    for (int _np = 0; _np < 2; ++_np) { \
        LDSM4(bh[buf][_np], stB0 + bOff + _np * (16 * ROWB) + (ks) * 32); \
        LDSM4(bl[buf][_np], stB1 + bOff + _np * (16 * ROWB) + (ks) * 32); } \
} while (0)

    for (int kt = 0; kt < NT; ++kt) {
        if (kt + 1 < NT) {
            load_stage(kt + 1, (kt + 1) & 1);
            asm volatile("cp.async.wait_group 1;" ::: "memory");
        } else {
            asm volatile("cp.async.wait_group 0;" ::: "memory");
        }
        __syncthreads();

        const uint32_t st   = sbase + (uint32_t)(kt & 1) * STAGEB;
        const uint32_t stA0 = st;
        const uint32_t stA1 = st + ATILEB;
        const uint32_t stB0 = st + 2 * ATILEB;
        const uint32_t stB1 = st + 2 * ATILEB + BTILEB;

        uint32_t ah[2][4][4], al[2][4][4], bh[2][2][4], bl[2][2][4];
        LDFRAGS(0, 0);

#pragma unroll
        for (int ks = 0; ks < 4; ++ks) {
            const int cur = ks & 1;
            const int nxt = cur ^ 1;
            if (ks < 3) {
                switch (ks + 1) {                 // immediate smem offsets
                    case 1: LDFRAGS(nxt, 1); break;
                    case 2: LDFRAGS(nxt, 2); break;
                    default: LDFRAGS(nxt, 3); break;
                }
            }
            // pass 1: Ahi x Bhi (16 distinct accumulators)
#pragma unroll
            for (int mt = 0; mt < 4; ++mt)
#pragma unroll
                for (int np = 0; np < 2; ++np) {
                    MMA16816(acc[mt][2 * np],     ah[cur][mt], bh[cur][np][0], bh[cur][np][1]);
                    MMA16816(acc[mt][2 * np + 1], ah[cur][mt], bh[cur][np][2], bh[cur][np][3]);
                }
            // pass 2: Ahi x Blo
#pragma unroll
            for (int mt = 0; mt < 4; ++mt)
#pragma unroll
                for (int np = 0; np < 2; ++np) {
                    MMA16816(acc[mt][2 * np],     ah[cur][mt], bl[cur][np][0], bl[cur][np][1]);
                    MMA16816(acc[mt][2 * np + 1], ah[cur][mt], bl[cur][np][2], bl[cur][np][3]);
                }
            // pass 3: Alo x Bhi
#pragma unroll
            for (int mt = 0; mt < 4; ++mt)
#pragma unroll
                for (int np = 0; np < 2; ++np) {
                    MMA16816(acc[mt][2 * np],     al[cur][mt], bh[cur][np][0], bh[cur][np][1]);
                    MMA16816(acc[mt][2 * np + 1], al[cur][mt], bh[cur][np][2], bh[cur][np][3]);
                }
        }

        __syncthreads();
    }

    const int rbase = bm + wm * 64 + (lane >> 2);
    const int cbase = bn + wn * 32 + (lane & 3) * 2;
#pragma unroll
    for (int mt = 0; mt < 4; ++mt) {
#pragma unroll
        for (int nt = 0; nt < 4; ++nt) {
            int grow = rbase + mt * 16;
            int gcol = cbase + nt * 8;
            *(float2*)(C + (size_t)grow * N + gcol) =
                make_float2(acc[mt][nt][0], acc[mt][nt][1]);
            *(float2*)(C + (size_t)(grow + 8) * N + gcol) =
                make_float2(acc[mt][nt][2], acc[mt][nt][3]);
        }
    }
#undef LDFRAGS
}

// ---------------------------------------------------------------------------
// fp32 -> (bf16 hi, bf16 lo) splits
// ---------------------------------------------------------------------------
__global__ void split_kernel(const float4* __restrict__ in,
                             __nv_bfloat162* __restrict__ hi,
                             __nv_bfloat162* __restrict__ lo, int n4)
{
    int i = blockIdx.x * blockDim.x + threadIdx.x;
    if (i >= n4) return;
    float4 v = in[i];
    __nv_bfloat16 h0 = __float2bfloat16(v.x);
    __nv_bfloat16 h1 = __float2bfloat16(v.y);
    __nv_bfloat16 h2 = __float2bfloat16(v.z);
    __nv_bfloat16 h3 = __float2bfloat16(v.w);
    __nv_bfloat16 l0 = __float2bfloat16(v.x - __bfloat162float(h0));
    __nv_bfloat16 l1 = __float2bfloat16(v.y - __bfloat162float(h1));
    __nv_bfloat16 l2 = __float2bfloat16(v.z - __bfloat162float(h2));
    __nv_bfloat16 l3 = __float2bfloat16(v.w - __bfloat162float(h3));
    hi[2 * i]     = __halves2bfloat162(h0, h1);
    hi[2 * i + 1] = __halves2bfloat162(h2, h3);
    lo[2 * i]     = __halves2bfloat162(l0, l1);
    lo[2 * i + 1] = __halves2bfloat162(l2, l3);
}

struct WPtrs { const float4* w[4]; };

__global__ void split_w_kernel(WPtrs wp, __nv_bfloat162* __restrict__ hi,
                               __nv_bfloat162* __restrict__ lo, int n4)
{
    int i = blockIdx.x * blockDim.x + threadIdx.x;
    if (i >= n4) return;
    int w = blockIdx.y;
    const float4* in = wp.w[w];
    size_t off = (size_t)w * n4;
    float4 v = in[i];
    __nv_bfloat16 h0 = __float2bfloat16(v.x);
    __nv_bfloat16 h1 = __float2bfloat16(v.y);
    __nv_bfloat16 h2 = __float2bfloat16(v.z);
    __nv_bfloat16 h3 = __float2bfloat16(v.w);
    __nv_bfloat16 l0 = __float2bfloat16(v.x - __bfloat162float(h0));
    __nv_bfloat16 l1 = __float2bfloat16(v.y - __bfloat162float(h1));
    __nv_bfloat16 l2 = __float2bfloat16(v.z - __bfloat162float(h2));
    __nv_bfloat16 l3 = __float2bfloat16(v.w - __bfloat162float(h3));
    hi[2 * (off + i)]     = __halves2bfloat162(h0, h1);
    hi[2 * (off + i) + 1] = __halves2bfloat162(h2, h3);
    lo[2 * (off + i)]     = __halves2bfloat162(l0, l1);
    lo[2 * (off + i) + 1] = __halves2bfloat162(l2, l3);
}

// ---------------------------------------------------------------------------
// Sliding-window attention; writes bf16 hi/lo directly (feeds final GEMM).
// ---------------------------------------------------------------------------
__global__ __launch_bounds__(128) void swa_kernel(
    const float* __restrict__ Q, const float* __restrict__ Kt,
    const float* __restrict__ Vt,
    __nv_bfloat16* __restrict__ Ohi, __nv_bfloat16* __restrict__ Olo)
{
    const int i = blockIdx.x;
    const int h = blockIdx.y;
    const int b = blockIdx.z;
    const int r = threadIdx.x;

    __shared__ __align__(16) float Kc[64][64];
    __shared__ __align__(16) float Vc[64][64];

    const float scale = 0.125f;

    float q[DK];
    const size_t rowoff = ((size_t)b * T_ + (size_t)i * BS_ + r) * D_ + (size_t)h * DK;
#pragma unroll
    for (int d = 0; d < DK; d += 4) {
        float4 t = *(const float4*)(Q + rowoff + d);
        q[d] = t.x; q[d + 1] = t.y; q[d + 2] = t.z; q[d + 3] = t.w;
    }

    float o[DK];
#pragma unroll
    for (int d = 0; d < DK; ++d) o[d] = 0.0f;
    float mval = -INFINITY;
    float l = 0.0f;

    const int base_t  = (i - 1) * BS_;
    const int cmin    = (i == 0) ? 128 : r;
    const int cmax    = r + 128;
    const int c_start = (i == 0) ? 128 : 0;

    const int sub = r >> 4;
    const int d4  = (r & 15) * 4;

    for (int c0 = c_start; c0 < 256; c0 += 64) {
        __syncthreads();
#pragma unroll
        for (int it = 0; it < 8; ++it) {
            int j  = it * 8 + sub;
            int tk = base_t + c0 + j;
            size_t off = ((size_t)b * T_ + tk) * D_ + (size_t)h * DK + d4;
            float4 kv = *(const float4*)(Kt + off);
            float4 vv = *(const float4*)(Vt + off);
            *(float4*)&Kc[j][d4] = kv;
            *(float4*)&Vc[j][d4] = vv;
        }
        __syncthreads();

        for (int j = 0; j < 64; ++j) {
            const int c = c0 + j;
            if (c < cmin || c > cmax) continue;

            float s0 = 0.0f, s1 = 0.0f;
#pragma unroll
            for (int d = 0; d < 32; d += 4) {
                float4 k4 = *(const float4*)&Kc[j][d];
                s0 += q[d] * k4.x + q[d + 1] * k4.y + q[d + 2] * k4.z + q[d + 3] * k4.w;
            }
#pragma unroll
            for (int d = 32; d < 64; d += 4) {
                float4 k4 = *(const float4*)&Kc[j][d];
                s1 += q[d] * k4.x + q[d + 1] * k4.y + q[d + 2] * k4.z + q[d + 3] * k4.w;
            }
            float s = (s0 + s1) * scale;

            if (s > mval) {
                float corr = __expf(mval - s);
                l *= corr;
#pragma unroll
                for (int d = 0; d < DK; ++d) o[d] *= corr;
                mval = s;
            }
            float p = __expf(s - mval);
            l += p;
#pragma unroll
            for (int d = 0; d < DK; d += 4) {
                float4 v4 = *(const float4*)&Vc[j][d];
                o[d]     += p * v4.x;
                o[d + 1] += p * v4.y;
                o[d + 2] += p * v4.z;
                o[d + 3] += p * v4.w;
            }
        }
    }

    const float inv = 1.0f / l;
    __nv_bfloat162* hp = (__nv_bfloat162*)(Ohi + rowoff);
    __nv_bfloat162* lp = (__nv_bfloat162*)(Olo + rowoff);
#pragma unroll
    for (int d = 0; d < DK; d += 2) {
        float a0 = o[d] * inv, a1 = o[d + 1] * inv;
        __nv_bfloat16 h0 = __float2bfloat16(a0);
        __nv_bfloat16 h1 = __float2bfloat16(a1);
        __nv_bfloat16 l0 = __float2bfloat16(a0 - __bfloat162float(h0));
        __nv_bfloat16 l1 = __float2bfloat16(a1 - __bfloat162float(h1));
        hp[d >> 1] = __halves2bfloat162(h0, h1);
        lp[d >> 1] = __halves2bfloat162(l0, l1);
    }
}

// ---------------------------------------------------------------------------
// Launch
// ---------------------------------------------------------------------------
extern "C" void kernel_launch(void* const* d_in, const int* in_sizes, int n_in,
                              void* d_out, int out_size)
{
    const float* x  = (const float*)d_in[0];
    float* out = (float*)d_out;

    float *qp, *kp, *vp;
    cudaGetSymbolAddress((void**)&qp,  g_Q);
    cudaGetSymbolAddress((void**)&kp,  g_K);
    cudaGetSymbolAddress((void**)&vp,  g_V);
    __nv_bfloat16 *xhi, *xlo, *aohi, *aolo, *whi, *wlo;
    cudaGetSymbolAddress((void**)&xhi,  g_xhi);
    cudaGetSymbolAddress((void**)&xlo,  g_xlo);
    cudaGetSymbolAddress((void**)&aohi, g_aohi);
    cudaGetSymbolAddress((void**)&aolo, g_aolo);
    cudaGetSymbolAddress((void**)&whi,  g_whi);
    cudaGetSymbolAddress((void**)&wlo,  g_wlo);

    cudaFuncSetAttribute(gemm_bf16x3, cudaFuncAttributeMaxDynamicSharedMemorySize, GSMEM);

    const int nX  = M_ * D_;
    const int nW  = D_ * D_;
    const int thr = 256;

    split_kernel<<<(nX / 4 + thr - 1) / thr, thr>>>(
        (const float4*)x, (__nv_bfloat162*)xhi, (__nv_bfloat162*)xlo, nX / 4);

    WPtrs wp;
    wp.w[0] = (const float4*)d_in[1];
    wp.w[1] = (const float4*)d_in[2];
    wp.w[2] = (const float4*)d_in[3];
    wp.w[3] = (const float4*)d_in[4];
    dim3 gw((nW / 4 + thr - 1) / thr, 4);
    split_w_kernel<<<gw, thr>>>(wp, (__nv_bfloat162*)whi, (__nv_bfloat162*)wlo, nW / 4);

    dim3 gg(D_ / 64, M_ / 128);         // (32, 64)
    gemm_bf16x3<<<gg, 128, GSMEM>>>(xhi, xlo, whi + 0 * (size_t)nW, wlo + 0 * (size_t)nW, qp, M_, D_, D_);
    gemm_bf16x3<<<gg, 128, GSMEM>>>(xhi, xlo, whi + 1 * (size_t)nW, wlo + 1 * (size_t)nW, kp, M_, D_, D_);
    gemm_bf16x3<<<gg, 128, GSMEM>>>(xhi, xlo, whi + 2 * (size_t)nW, wlo + 2 * (size_t)nW, vp, M_, D_, D_);

    dim3 ga(NB, H_, B_);
    swa_kernel<<<ga, 128>>>(qp, kp, vp, aohi, aolo);

    gemm_bf16x3<<<gg, 128, GSMEM>>>(aohi, aolo, whi + 3 * (size_t)nW, wlo + 3 * (size_t)nW, out, M_, D_, D_);
}